// round 12
// baseline (speedup 1.0000x reference)
#include <cuda_runtime.h>
#include <cuda_bf16.h>
#include <cstdint>

// ---------------------------------------------------------------------------
// TransducerPrediction: embed lookup + 2-layer LSTM (Keras gate order i,f,g,o)
// B=64, T=512, EMBED=512, UNITS=1024, 4U=4096.
//
// Graph (6 nodes):
//   1) gemm_tf32: xz0 = embed[tokens] @ W0 + b0
//   2) zero_cnt
//   3) lstm_rec : layer-0 recurrence -> g_h0
//   4) gemm_tf32: xz1 = g_h0 @ W1 + b1
//   5) zero_cnt
//   6) lstm_rec : layer-1 recurrence -> d_out
//
// R12 change vs R11: counter polling is done by ONE thread per CTA, folded
// into the pipeline's existing __syncthreads points. R11 had all 512 threads
// spinning ld.acquire.gpu on 8 L2 lines (65K spinners), serializing at the
// LTS and delaying the release writes themselves.
// ---------------------------------------------------------------------------

#define BATCH   64
#define SEQT    512
#define EMBED   512
#define UNITS   1024
#define GATES   4096
#define BT      (BATCH*SEQT)

#define RT_NCTA    128
#define RT_THREADS 512

// smem layout (bytes):
//   UsB  : 0      .. 131072   (1024x32 tf32 U slice, float2-packed frags)
//   Hs   : 131072 .. 198656   (2 x [64][132] f32 h-chunk buffers)
//   xzs  : 198656 .. 207872   ([64][36] f32 staged gates)
//   zbuf : 207872 .. 216320   ([64][33] f32 z spill)
#define SM_US    0
#define SM_HS    131072
#define SM_HSZ   33792          // 64*132*4 per buffer
#define SM_XZ    198656
#define SM_ZB    207872
#define REC_SMEM_BYTES 216320

// ---- device scratch ----
__device__ __align__(16) float g_xz[(size_t)BT * GATES];
__device__ __align__(16) float g_h0[(size_t)BT * UNITS];
__device__ __align__(16) float g_hbuf[2][BATCH * UNITS];
__device__ unsigned g_cnt[8 * 32];   // 8 chunk-group counters, 128B apart

// ---------------------------------------------------------------------------
// helpers
// ---------------------------------------------------------------------------
__device__ __forceinline__ float tf32r(float x) {
    unsigned u;
    asm("cvt.rna.tf32.f32 %0, %1;" : "=r"(u) : "f"(x));
    return __uint_as_float(u);
}

__device__ __forceinline__ void mma_m16n8k8_tf32(float* c, float2 a02, float2 a13, float2 b01) {
    unsigned a0 = __float_as_uint(a02.x), a1 = __float_as_uint(a13.x);
    unsigned a2 = __float_as_uint(a02.y), a3 = __float_as_uint(a13.y);
    unsigned b0 = __float_as_uint(b01.x), b1 = __float_as_uint(b01.y);
    asm volatile(
        "mma.sync.aligned.m16n8k8.row.col.f32.tf32.tf32.f32 "
        "{%0,%1,%2,%3}, {%4,%5,%6,%7}, {%8,%9}, {%0,%1,%2,%3};\n"
        : "+f"(c[0]), "+f"(c[1]), "+f"(c[2]), "+f"(c[3])
        : "r"(a0), "r"(a1), "r"(a2), "r"(a3), "r"(b0), "r"(b1));
}

__device__ __forceinline__ float sigmoidf_(float x) {
    return 1.0f / (1.0f + __expf(-x));
}

#define CP_ASYNC16(dst_u32, src_ptr) \
    asm volatile("cp.async.cg.shared.global [%0], [%1], 16;\n" \
                 :: "r"(dst_u32), "l"(src_ptr))
#define CP_COMMIT() asm volatile("cp.async.commit_group;\n" ::: "memory")
#define CP_WAIT(n)  asm volatile("cp.async.wait_group %0;\n" :: "n"(n) : "memory")

__device__ __forceinline__ void arrive_release(unsigned* p) {
    asm volatile("red.release.gpu.global.add.u32 [%0], %1;\n" :: "l"(p), "r"(1u) : "memory");
}
__device__ __forceinline__ void poll_acquire(const unsigned* p, unsigned target) {
    unsigned v;
    do {
        asm volatile("ld.acquire.gpu.global.u32 %0, [%1];\n" : "=r"(v) : "l"(p) : "memory");
    } while (v < target);
}

// ---------------------------------------------------------------------------
// Big GEMM: C[M=BT x 4096] = Arows[M x K] @ Bmat[K x 4096] + bias
// (unchanged from the passing round-10/11 kernel)
// ---------------------------------------------------------------------------
__global__ __launch_bounds__(256)
void gemm_tf32(const float* __restrict__ A,
               const int*   __restrict__ tokens,
               const float* __restrict__ emb,
               const float* __restrict__ Bmat,
               const float* __restrict__ bias,
               float*       __restrict__ C,
               int K)
{
    __shared__ float2 As[4 * 128 * 4];
    __shared__ float2 Bs[4 * 128 * 4];

    const int tid  = threadIdx.x;
    const int lane = tid & 31;
    const int wid  = tid >> 5;
    const int gid  = lane >> 2;
    const int tig  = lane & 3;

    const int r0 = blockIdx.y * 128;
    const int n0 = blockIdx.x * 128;
    const int wm = wid >> 2;
    const int wn = wid & 3;

    float c[4][4][4];
    #pragma unroll
    for (int i = 0; i < 4; i++)
        #pragma unroll
        for (int j = 0; j < 4; j++)
            #pragma unroll
            for (int k = 0; k < 4; k++) c[i][j][k] = 0.0f;

    for (int k0 = 0; k0 < K; k0 += 32) {
        #pragma unroll 4
        for (int idx = tid; idx < 128 * 32; idx += 256) {
            int row = idx >> 5, kk = idx & 31;
            const float* src = tokens
                ? emb + (size_t)tokens[r0 + row] * EMBED
                : A   + (size_t)(r0 + row) * K;
            float v = tf32r(src[k0 + kk]);
            ((float*)&As[((kk >> 3) * 128 + row) * 4 + (kk & 3)])[(kk >> 2) & 1] = v;
        }
        #pragma unroll 4
        for (int idx = tid; idx < 32 * 128; idx += 256) {
            int kk = idx >> 7, col = idx & 127;
            float v = tf32r(Bmat[(size_t)(k0 + kk) * GATES + n0 + col]);
            ((float*)&Bs[((kk >> 3) * 128 + col) * 4 + (kk & 3)])[(kk >> 2) & 1] = v;
        }
        __syncthreads();

        #pragma unroll
        for (int kc = 0; kc < 4; kc++) {
            float2 a02[4], a13[4];
            #pragma unroll
            for (int mf = 0; mf < 4; mf++) {
                int m = wm * 64 + mf * 16;
                a02[mf] = As[(kc * 128 + m + gid) * 4 + tig];
                a13[mf] = As[(kc * 128 + m + 8 + gid) * 4 + tig];
            }
            #pragma unroll
            for (int nf = 0; nf < 4; nf++) {
                int n = wn * 32 + nf * 8;
                float2 b01 = Bs[(kc * 128 + n + gid) * 4 + tig];
                #pragma unroll
                for (int mf = 0; mf < 4; mf++)
                    mma_m16n8k8_tf32(c[mf][nf], a02[mf], a13[mf], b01);
            }
        }
        __syncthreads();
    }

    #pragma unroll
    for (int mf = 0; mf < 4; mf++) {
        int row = r0 + wm * 64 + mf * 16 + gid;
        #pragma unroll
        for (int nf = 0; nf < 4; nf++) {
            int col = n0 + wn * 32 + nf * 8 + tig * 2;
            float bb0 = bias[col], bb1 = bias[col + 1];
            float2 v0 = make_float2(c[mf][nf][0] + bb0, c[mf][nf][1] + bb1);
            float2 v1 = make_float2(c[mf][nf][2] + bb0, c[mf][nf][3] + bb1);
            *(float2*)&C[(size_t)row * GATES + col]       = v0;
            *(float2*)&C[(size_t)(row + 8) * GATES + col] = v1;
        }
    }
}

// ---------------------------------------------------------------------------
// zero the chunk-group counters (runs before each lstm_rec launch)
// ---------------------------------------------------------------------------
__global__ void zero_cnt() {
    if (threadIdx.x < 8 * 32) g_cnt[threadIdx.x] = 0;
}

// ---------------------------------------------------------------------------
// Persistent recurrent kernel. 128 CTAs x 512 threads, 1 CTA/SM.
// CTA owns units [u0,u0+8) -> 32 gate cols; U slice resident in smem.
// Per-chunk-group producer counters; ONLY tid 0 polls, folded into the
// pipeline's existing __syncthreads.
// ---------------------------------------------------------------------------
__global__ __launch_bounds__(RT_THREADS, 1)
void lstm_rec(const float* __restrict__ U,    // [1024][4096]
              const float* __restrict__ xz,   // [B][T][4096]
              float*       __restrict__ hall, // [B][T][1024]
              int T)
{
    extern __shared__ char smem_c[];
    float2* UsB  = (float2*)(smem_c + SM_US);
    float*  Hs   = (float*) (smem_c + SM_HS);
    float*  xzs  = (float*) (smem_c + SM_XZ);
    float*  zbuf = (float*) (smem_c + SM_ZB);
    const unsigned smem_u32 = (unsigned)__cvta_generic_to_shared(smem_c);

    const int tid  = threadIdx.x;
    const int lane = tid & 31;
    const int wid  = tid >> 5;
    const int gid  = lane >> 2;
    const int tig  = lane & 3;
    const int cta  = blockIdx.x;
    const int u0   = cta * 8;
    const int grp  = cta >> 4;          // this CTA's chunk group (h units u0/128)

    // one-time: load + tf32-round the CTA's U slice into smem (frag-packed)
    for (int idx = tid; idx < 1024 * 32; idx += RT_THREADS) {
        int k = idx >> 5, cc = idx & 31;
        int G = (cc >> 3) * UNITS + u0 + (cc & 7);
        float v = tf32r(U[(size_t)k * GATES + G]);
        int kcg = k >> 3, kk = k & 7;
        ((float*)&UsB[(kcg * 32 + cc) * 4 + (kk & 3)])[kk >> 2] = v;
    }

    // produce h_0 = 0 for this CTA's slice, then arrive
    {
        int b = tid >> 3, u = tid & 7;       // 512 threads = 64 b x 8 u
        g_hbuf[0][b * UNITS + u0 + u] = 0.0f;
    }
    __syncthreads();
    if (tid == 0) arrive_release(&g_cnt[grp * 32]);

    float creg = 0.0f;                       // cell state, 1 (b,u) pair/thread
    const int ab = tid >> 3, au = tid & 7;   // activation pair

    const int wm = wid >> 2;                 // 0..3 : 16 batches
    const int wn = wid & 3;                  // 0..3 : 8 cols
    const int m0 = wm * 16;

    for (int t = 0; t < T; ++t) {
        const float* hcur = g_hbuf[t & 1];
        const unsigned target = 16u * (unsigned)(t + 1);

        // -- stage xz gates for this step (no h dependency; overlaps chunk loop)
        {
            int b = tid >> 3, r = tid & 7, g = r >> 1, h4 = r & 1;
            const float* src = xz + ((size_t)(b * T + t)) * GATES + g * UNITS + u0 + h4 * 4;
            unsigned dst = smem_u32 + SM_XZ + (b * 36 + g * 8 + h4 * 4) * 4;
            CP_ASYNC16(dst, src);
            CP_COMMIT();                      // group: XZ
        }

        // -- wait for chunk groups 0,1 (tid 0 polls; others park at the bar)
        if (tid == 0) {
            poll_acquire(&g_cnt[0 * 32], target);
            poll_acquire(&g_cnt[1 * 32], target);
        }
        __syncthreads();

        // -- prefetch h chunks 0,1
        #pragma unroll
        for (int pc = 0; pc < 2; ++pc) {
            #pragma unroll
            for (int j = 0; j < 4; ++j) {
                int i = tid + j * RT_THREADS;         // 2048 16B copies
                int row = i >> 5, seg = i & 31;
                unsigned dst = smem_u32 + SM_HS + (pc & 1) * SM_HSZ + row * 528 + seg * 16;
                CP_ASYNC16(dst, hcur + row * UNITS + pc * 128 + seg * 4);
            }
            CP_COMMIT();                      // groups: H0, H1
        }

        float acc[4] = {0.0f, 0.0f, 0.0f, 0.0f};

        for (int c = 0; c < 8; ++c) {
            if (c < 7) { CP_WAIT(1); } else { CP_WAIT(0); }
            // fold next-chunk poll into this barrier: tid 0 spins, rest wait
            if (tid == 0 && c + 2 < 8) poll_acquire(&g_cnt[(c + 2) * 32], target);
            __syncthreads();                  // chunk c visible + poll done

            const float* H = Hs + (c & 1) * (SM_HSZ / 4);
            #pragma unroll
            for (int kc = 0; kc < 16; ++kc) {
                const float* r0p = H + (m0 + gid) * 132 + kc * 8;
                const float* r1p = H + (m0 + 8 + gid) * 132 + kc * 8;
                float2 a02 = make_float2(r0p[tig], r0p[tig + 4]);
                float2 a13 = make_float2(r1p[tig], r1p[tig + 4]);
                float2 b01 = UsB[(((c * 16 + kc) * 32) + wn * 8 + gid) * 4 + tig];
                mma_m16n8k8_tf32(acc, a02, a13, b01);
            }

            if (c + 2 < 8) {
                __syncthreads();              // buffer (c&1) free for reuse
                #pragma unroll
                for (int j = 0; j < 4; ++j) {
                    int i = tid + j * RT_THREADS;
                    int row = i >> 5, seg = i & 31;
                    unsigned dst = smem_u32 + SM_HS + (c & 1) * SM_HSZ + row * 528 + seg * 16;
                    CP_ASYNC16(dst, hcur + row * UNITS + (c + 2) * 128 + seg * 4);
                }
                CP_COMMIT();
            }
        }

        // -- spill z to smem for cross-thread gate combine
        {
            int col = wn * 8 + tig * 2;
            zbuf[(m0 + gid) * 33 + col]         = acc[0];
            zbuf[(m0 + gid) * 33 + col + 1]     = acc[1];
            zbuf[(m0 + 8 + gid) * 33 + col]     = acc[2];
            zbuf[(m0 + 8 + gid) * 33 + col + 1] = acc[3];
        }
        __syncthreads();

        // -- activations + state update (xz already staged in smem)
        {
            float zi = zbuf[ab * 33 + au]      + xzs[ab * 36 + au];
            float zf = zbuf[ab * 33 + 8 + au]  + xzs[ab * 36 + 8 + au];
            float zg = zbuf[ab * 33 + 16 + au] + xzs[ab * 36 + 16 + au];
            float zo = zbuf[ab * 33 + 24 + au] + xzs[ab * 36 + 24 + au];
            float ig = sigmoidf_(zi);
            float fg = sigmoidf_(zf);
            float gg = tanhf(zg);
            float og = sigmoidf_(zo);
            float cx = fg * creg + ig * gg;
            creg = cx;
            float h = og * tanhf(cx);
            hall[((size_t)(ab * T + t)) * UNITS + u0 + au] = h;
            g_hbuf[(t + 1) & 1][ab * UNITS + u0 + au] = tf32r(h);
        }
        __syncthreads();                      // all slice writes done; xzs free
        if (tid == 0) arrive_release(&g_cnt[grp * 32]);
    }
}

// ---------------------------------------------------------------------------
// launcher
// ---------------------------------------------------------------------------
extern "C" void kernel_launch(void* const* d_in, const int* in_sizes, int n_in,
                              void* d_out, int out_size)
{
    const int*   tokens = (const int*)  d_in[0];
    const float* emb    = (const float*)d_in[1];
    const float* W0     = (const float*)d_in[2];
    const float* U0     = (const float*)d_in[3];
    const float* b0     = (const float*)d_in[4];
    const float* W1     = (const float*)d_in[5];
    const float* U1     = (const float*)d_in[6];
    const float* b1     = (const float*)d_in[7];
    float* out = (float*)d_out;

    float *xz = nullptr, *h0 = nullptr;
    cudaGetSymbolAddress((void**)&xz, g_xz);
    cudaGetSymbolAddress((void**)&h0, g_h0);

    cudaFuncSetAttribute(lstm_rec, cudaFuncAttributeMaxDynamicSharedMemorySize,
                         REC_SMEM_BYTES);

    dim3 ggrid(GATES / 128, BT / 128);

    // Phase A: xz0 = embed[tokens] @ W0 + b0
    gemm_tf32<<<ggrid, 256>>>(nullptr, tokens, emb, W0, b0, xz, EMBED);
    // Phase B: layer-0 recurrence
    zero_cnt<<<1, 256>>>();
    lstm_rec<<<RT_NCTA, RT_THREADS, REC_SMEM_BYTES>>>(U0, xz, h0, SEQT);
    // Phase C: xz1 = h0 @ W1 + b1
    gemm_tf32<<<ggrid, 256>>>(h0, nullptr, nullptr, W1, b1, xz, UNITS);
    // Phase D: layer-1 recurrence -> output
    zero_cnt<<<1, 256>>>();
    lstm_rec<<<RT_NCTA, RT_THREADS, REC_SMEM_BYTES>>>(U1, xz, out, SEQT);
}

// round 15
// speedup vs baseline: 1.2609x; 1.2609x over previous
#include <cuda_runtime.h>
#include <cuda_bf16.h>
#include <cstdint>

// ---------------------------------------------------------------------------
// TransducerPrediction: embed lookup + 2-layer LSTM (Keras gate order i,f,g,o)
// B=64, T=512, EMBED=512, UNITS=1024, 4U=4096.
//
// Graph (6 nodes):
//   1) gemm_tf32: xz0 = embed[tokens] @ W0 + b0
//   2) zero_cnt
//   3) lstm_rec : layer-0 recurrence -> g_h0
//   4) gemm_tf32: xz1 = g_h0 @ W1 + b1
//   5) zero_cnt
//   6) lstm_rec : layer-1 recurrence -> d_out
//
// R13 change vs R12: lstm_rec inner loop re-tiled from m16n8-per-warp
// (2.67 FLOP per smem byte, single acc chain) to 2m x 8k warp grid with
// m32n32 warp tiles and k-split (8 FLOP/B, 8 acc chains), with a once-per-
// step smem reduction over the 8 k-partials. Polling is one parallel poll
// point per step (warp0 lanes 0..7), no per-chunk polls.
// ---------------------------------------------------------------------------

#define BATCH   64
#define SEQT    512
#define EMBED   512
#define UNITS   1024
#define GATES   4096
#define BT      (BATCH*SEQT)

#define RT_NCTA    128
#define RT_THREADS 512

// smem layout (bytes):
//   UsB  : 0      .. 131072   (1024x32 tf32 U slice, float2-packed frags)
//   Hs   : 131072 .. 200704   (2 x [64][132] f32 h-chunk buffers; overlaid by
//                              zred[8][64][34] f32 partials after last chunk)
//   xzs  : 200704 .. 209920   ([64][36] f32 staged gates)
#define SM_US    0
#define SM_HS    131072
#define SM_HSZ   33792          // 64*132*4 per staging buffer
#define SM_XZ    200704
#define REC_SMEM_BYTES 209920

// ---- device scratch ----
__device__ __align__(16) float g_xz[(size_t)BT * GATES];
__device__ __align__(16) float g_h0[(size_t)BT * UNITS];
__device__ __align__(16) float g_hbuf[2][BATCH * UNITS];
__device__ unsigned g_cnt[8 * 32];   // 8 chunk-group counters, 128B apart

// ---------------------------------------------------------------------------
// helpers
// ---------------------------------------------------------------------------
__device__ __forceinline__ float tf32r(float x) {
    unsigned u;
    asm("cvt.rna.tf32.f32 %0, %1;" : "=r"(u) : "f"(x));
    return __uint_as_float(u);
}

__device__ __forceinline__ void mma_m16n8k8_tf32(float* c, float2 a02, float2 a13, float2 b01) {
    unsigned a0 = __float_as_uint(a02.x), a1 = __float_as_uint(a13.x);
    unsigned a2 = __float_as_uint(a02.y), a3 = __float_as_uint(a13.y);
    unsigned b0 = __float_as_uint(b01.x), b1 = __float_as_uint(b01.y);
    asm volatile(
        "mma.sync.aligned.m16n8k8.row.col.f32.tf32.tf32.f32 "
        "{%0,%1,%2,%3}, {%4,%5,%6,%7}, {%8,%9}, {%0,%1,%2,%3};\n"
        : "+f"(c[0]), "+f"(c[1]), "+f"(c[2]), "+f"(c[3])
        : "r"(a0), "r"(a1), "r"(a2), "r"(a3), "r"(b0), "r"(b1));
}

__device__ __forceinline__ float sigmoidf_(float x) {
    return 1.0f / (1.0f + __expf(-x));
}

#define CP_ASYNC16(dst_u32, src_ptr) \
    asm volatile("cp.async.cg.shared.global [%0], [%1], 16;\n" \
                 :: "r"(dst_u32), "l"(src_ptr))
#define CP_COMMIT() asm volatile("cp.async.commit_group;\n" ::: "memory")
#define CP_WAIT(n)  asm volatile("cp.async.wait_group %0;\n" :: "n"(n) : "memory")

__device__ __forceinline__ void arrive_release(unsigned* p) {
    asm volatile("red.release.gpu.global.add.u32 [%0], %1;\n" :: "l"(p), "r"(1u) : "memory");
}
__device__ __forceinline__ void poll_acquire(const unsigned* p, unsigned target) {
    unsigned v;
    do {
        asm volatile("ld.acquire.gpu.global.u32 %0, [%1];\n" : "=r"(v) : "l"(p) : "memory");
    } while (v < target);
}

// ---------------------------------------------------------------------------
// Big GEMM: C[M=BT x 4096] = Arows[M x K] @ Bmat[K x 4096] + bias
// (unchanged from the passing round-10/11 kernel)
// ---------------------------------------------------------------------------
__global__ __launch_bounds__(256)
void gemm_tf32(const float* __restrict__ A,
               const int*   __restrict__ tokens,
               const float* __restrict__ emb,
               const float* __restrict__ Bmat,
               const float* __restrict__ bias,
               float*       __restrict__ C,
               int K)
{
    __shared__ float2 As[4 * 128 * 4];
    __shared__ float2 Bs[4 * 128 * 4];

    const int tid  = threadIdx.x;
    const int lane = tid & 31;
    const int wid  = tid >> 5;
    const int gid  = lane >> 2;
    const int tig  = lane & 3;

    const int r0 = blockIdx.y * 128;
    const int n0 = blockIdx.x * 128;
    const int wm = wid >> 2;
    const int wn = wid & 3;

    float c[4][4][4];
    #pragma unroll
    for (int i = 0; i < 4; i++)
        #pragma unroll
        for (int j = 0; j < 4; j++)
            #pragma unroll
            for (int k = 0; k < 4; k++) c[i][j][k] = 0.0f;

    for (int k0 = 0; k0 < K; k0 += 32) {
        #pragma unroll 4
        for (int idx = tid; idx < 128 * 32; idx += 256) {
            int row = idx >> 5, kk = idx & 31;
            const float* src = tokens
                ? emb + (size_t)tokens[r0 + row] * EMBED
                : A   + (size_t)(r0 + row) * K;
            float v = tf32r(src[k0 + kk]);
            ((float*)&As[((kk >> 3) * 128 + row) * 4 + (kk & 3)])[(kk >> 2) & 1] = v;
        }
        #pragma unroll 4
        for (int idx = tid; idx < 32 * 128; idx += 256) {
            int kk = idx >> 7, col = idx & 127;
            float v = tf32r(Bmat[(size_t)(k0 + kk) * GATES + n0 + col]);
            ((float*)&Bs[((kk >> 3) * 128 + col) * 4 + (kk & 3)])[(kk >> 2) & 1] = v;
        }
        __syncthreads();

        #pragma unroll
        for (int kc = 0; kc < 4; kc++) {
            float2 a02[4], a13[4];
            #pragma unroll
            for (int mf = 0; mf < 4; mf++) {
                int m = wm * 64 + mf * 16;
                a02[mf] = As[(kc * 128 + m + gid) * 4 + tig];
                a13[mf] = As[(kc * 128 + m + 8 + gid) * 4 + tig];
            }
            #pragma unroll
            for (int nf = 0; nf < 4; nf++) {
                int n = wn * 32 + nf * 8;
                float2 b01 = Bs[(kc * 128 + n + gid) * 4 + tig];
                #pragma unroll
                for (int mf = 0; mf < 4; mf++)
                    mma_m16n8k8_tf32(c[mf][nf], a02[mf], a13[mf], b01);
            }
        }
        __syncthreads();
    }

    #pragma unroll
    for (int mf = 0; mf < 4; mf++) {
        int row = r0 + wm * 64 + mf * 16 + gid;
        #pragma unroll
        for (int nf = 0; nf < 4; nf++) {
            int col = n0 + wn * 32 + nf * 8 + tig * 2;
            float bb0 = bias[col], bb1 = bias[col + 1];
            float2 v0 = make_float2(c[mf][nf][0] + bb0, c[mf][nf][1] + bb1);
            float2 v1 = make_float2(c[mf][nf][2] + bb0, c[mf][nf][3] + bb1);
            *(float2*)&C[(size_t)row * GATES + col]       = v0;
            *(float2*)&C[(size_t)(row + 8) * GATES + col] = v1;
        }
    }
}

// ---------------------------------------------------------------------------
// zero the chunk-group counters (runs before each lstm_rec launch)
// ---------------------------------------------------------------------------
__global__ void zero_cnt() {
    if (threadIdx.x < 8 * 32) g_cnt[threadIdx.x] = 0;
}

// ---------------------------------------------------------------------------
// Persistent recurrent kernel. 128 CTAs x 512 threads, 1 CTA/SM.
// CTA owns units [u0,u0+8) -> 32 gate cols; U slice resident in smem.
// Warp grid: 2 m-warps x 8 k-warps; warp tile m32 x n32, 2 kc per chunk.
// Partial z accs (per k-warp) reduced once per step via smem.
// ---------------------------------------------------------------------------
__global__ __launch_bounds__(RT_THREADS, 1)
void lstm_rec(const float* __restrict__ U,    // [1024][4096]
              const float* __restrict__ xz,   // [B][T][4096]
              float*       __restrict__ hall, // [B][T][1024]
              int T)
{
    extern __shared__ char smem_c[];
    float2* UsB  = (float2*)(smem_c + SM_US);
    float*  Hs   = (float*) (smem_c + SM_HS);
    float*  zred = (float*) (smem_c + SM_HS);   // overlays Hs after last chunk
    float*  xzs  = (float*) (smem_c + SM_XZ);
    const unsigned smem_u32 = (unsigned)__cvta_generic_to_shared(smem_c);

    const int tid  = threadIdx.x;
    const int lane = tid & 31;
    const int wid  = tid >> 5;
    const int gid  = lane >> 2;
    const int tig  = lane & 3;
    const int cta  = blockIdx.x;
    const int u0   = cta * 8;
    const int grp  = cta >> 4;          // this CTA's chunk group (h units u0/128)

    // one-time: load + tf32-round the CTA's U slice into smem (frag-packed)
    for (int idx = tid; idx < 1024 * 32; idx += RT_THREADS) {
        int k = idx >> 5, cc = idx & 31;
        int G = (cc >> 3) * UNITS + u0 + (cc & 7);
        float v = tf32r(U[(size_t)k * GATES + G]);
        int kcg = k >> 3, kk = k & 7;
        ((float*)&UsB[(kcg * 32 + cc) * 4 + (kk & 3)])[kk >> 2] = v;
    }

    // produce h_0 = 0 for this CTA's slice, then arrive
    {
        int b = tid >> 3, u = tid & 7;       // 512 threads = 64 b x 8 u
        g_hbuf[0][b * UNITS + u0 + u] = 0.0f;
    }
    __syncthreads();
    if (tid == 0) arrive_release(&g_cnt[grp * 32]);

    float creg = 0.0f;                       // cell state, 1 (b,u) pair/thread
    const int ab = tid >> 3, au = tid & 7;   // activation pair

    const int kw = wid & 7;                  // k-warp: kc pair {2kw, 2kw+1} per chunk
    const int mw = wid >> 3;                 // m-warp: 32 batches
    const int m0 = mw * 32;

    for (int t = 0; t < T; ++t) {
        const float* hcur = g_hbuf[t & 1];
        const unsigned target = 16u * (unsigned)(t + 1);

        // -- stage xz gates for this step (no h dependency; overlaps chunk loop)
        {
            int b = tid >> 3, r = tid & 7, g = r >> 1, h4 = r & 1;
            const float* src = xz + ((size_t)(b * T + t)) * GATES + g * UNITS + u0 + h4 * 4;
            unsigned dst = smem_u32 + SM_XZ + (b * 36 + g * 8 + h4 * 4) * 4;
            CP_ASYNC16(dst, src);
            CP_COMMIT();                      // group: XZ
        }

        // -- single poll point: warp0 lanes 0..7 poll the 8 groups in parallel
        if (wid == 0 && lane < 8) poll_acquire(&g_cnt[lane * 32], target);
        __syncthreads();

        // -- prefetch h chunks 0,1
        #pragma unroll
        for (int pc = 0; pc < 2; ++pc) {
            #pragma unroll
            for (int j = 0; j < 4; ++j) {
                int i = tid + j * RT_THREADS;         // 2048 16B copies
                int row = i >> 5, seg = i & 31;
                unsigned dst = smem_u32 + SM_HS + (pc & 1) * SM_HSZ + row * 528 + seg * 16;
                CP_ASYNC16(dst, hcur + row * UNITS + pc * 128 + seg * 4);
            }
            CP_COMMIT();                      // groups: H0, H1
        }

        float acc[2][4][4];
        #pragma unroll
        for (int mf = 0; mf < 2; mf++)
            #pragma unroll
            for (int nt = 0; nt < 4; nt++)
                #pragma unroll
                for (int q = 0; q < 4; q++) acc[mf][nt][q] = 0.0f;

        for (int c = 0; c < 8; ++c) {
            if (c < 7) { CP_WAIT(1); } else { CP_WAIT(0); }
            __syncthreads();                  // chunk c visible CTA-wide

            const float* H = Hs + (c & 1) * (SM_HSZ / 4);
            #pragma unroll
            for (int j = 0; j < 2; ++j) {
                const int kl = kw * 2 + j;            // local kc in chunk
                const int kcg = c * 16 + kl;
                const float* Hb = H + kl * 8 + tig;
                float2 a02[2], a13[2];
                #pragma unroll
                for (int mf = 0; mf < 2; ++mf) {
                    const float* r0p = Hb + (m0 + mf * 16 + gid) * 132;
                    a02[mf] = make_float2(r0p[0], r0p[4]);
                    a13[mf] = make_float2(r0p[8 * 132], r0p[8 * 132 + 4]);
                }
                #pragma unroll
                for (int nt = 0; nt < 4; ++nt) {
                    float2 b01 = UsB[(kcg * 32 + nt * 8 + gid) * 4 + tig];
                    mma_m16n8k8_tf32(acc[0][nt], a02[0], a13[0], b01);
                    mma_m16n8k8_tf32(acc[1][nt], a02[1], a13[1], b01);
                }
            }

            if (c + 2 < 8) {
                __syncthreads();              // buffer (c&1) free for reuse
                #pragma unroll
                for (int j = 0; j < 4; ++j) {
                    int i = tid + j * RT_THREADS;
                    int row = i >> 5, seg = i & 31;
                    unsigned dst = smem_u32 + SM_HS + (c & 1) * SM_HSZ + row * 528 + seg * 16;
                    CP_ASYNC16(dst, hcur + row * UNITS + (c + 2) * 128 + seg * 4);
                }
                CP_COMMIT();
            }
        }

        __syncthreads();                      // Hs staging dead -> zred may reuse

        // -- store per-k-warp partials: zred[kw][row(64)][col(34 pitch)]
        #pragma unroll
        for (int mf = 0; mf < 2; ++mf) {
            int row = m0 + mf * 16 + gid;
            #pragma unroll
            for (int nt = 0; nt < 4; ++nt) {
                int col = nt * 8 + tig * 2;
                *(float2*)&zred[kw * 2176 + row * 34 + col] =
                    make_float2(acc[mf][nt][0], acc[mf][nt][1]);
                *(float2*)&zred[kw * 2176 + (row + 8) * 34 + col] =
                    make_float2(acc[mf][nt][2], acc[mf][nt][3]);
            }
        }
        __syncthreads();

        // -- k-reduction + activations + state update
        {
            float z[4];
            #pragma unroll
            for (int g = 0; g < 4; ++g) {
                float s = 0.0f;
                #pragma unroll
                for (int k = 0; k < 8; ++k)
                    s += zred[k * 2176 + ab * 34 + g * 8 + au];
                z[g] = s + xzs[ab * 36 + g * 8 + au];
            }
            float ig = sigmoidf_(z[0]);
            float fg = sigmoidf_(z[1]);
            float gg = tanhf(z[2]);
            float og = sigmoidf_(z[3]);
            float cx = fg * creg + ig * gg;
            creg = cx;
            float h = og * tanhf(cx);
            hall[((size_t)(ab * T + t)) * UNITS + u0 + au] = h;
            g_hbuf[(t + 1) & 1][ab * UNITS + u0 + au] = tf32r(h);
        }
        __syncthreads();                      // all slice writes done; smem free
        if (tid == 0) arrive_release(&g_cnt[grp * 32]);
    }
}

// ---------------------------------------------------------------------------
// launcher
// ---------------------------------------------------------------------------
extern "C" void kernel_launch(void* const* d_in, const int* in_sizes, int n_in,
                              void* d_out, int out_size)
{
    const int*   tokens = (const int*)  d_in[0];
    const float* emb    = (const float*)d_in[1];
    const float* W0     = (const float*)d_in[2];
    const float* U0     = (const float*)d_in[3];
    const float* b0     = (const float*)d_in[4];
    const float* W1     = (const float*)d_in[5];
    const float* U1     = (const float*)d_in[6];
    const float* b1     = (const float*)d_in[7];
    float* out = (float*)d_out;

    float *xz = nullptr, *h0 = nullptr;
    cudaGetSymbolAddress((void**)&xz, g_xz);
    cudaGetSymbolAddress((void**)&h0, g_h0);

    cudaFuncSetAttribute(lstm_rec, cudaFuncAttributeMaxDynamicSharedMemorySize,
                         REC_SMEM_BYTES);

    dim3 ggrid(GATES / 128, BT / 128);

    // Phase A: xz0 = embed[tokens] @ W0 + b0
    gemm_tf32<<<ggrid, 256>>>(nullptr, tokens, emb, W0, b0, xz, EMBED);
    // Phase B: layer-0 recurrence
    zero_cnt<<<1, 256>>>();
    lstm_rec<<<RT_NCTA, RT_THREADS, REC_SMEM_BYTES>>>(U0, xz, h0, SEQT);
    // Phase C: xz1 = h0 @ W1 + b1
    gemm_tf32<<<ggrid, 256>>>(h0, nullptr, nullptr, W1, b1, xz, UNITS);
    // Phase D: layer-1 recurrence -> output
    zero_cnt<<<1, 256>>>();
    lstm_rec<<<RT_NCTA, RT_THREADS, REC_SMEM_BYTES>>>(U1, xz, out, SEQT);
}